// round 5
// baseline (speedup 1.0000x reference)
#include <cuda_runtime.h>

// ECE loss: logits (8,19,512,1024) f32, labels (8,512,1024) int32 -> scalar f32.
// (Harness stores labels as int32; the int64-interpretation read pattern was
//  in-bounds yet R1 faulted -> buffer must be 4B/pixel.)
//
// ECE = (1/total) * sum_bins | sum_{pixel in bin} (conf - correct) |
// conf = max softmax = 1 / sum_c exp(x_c - max); correct = (x[label] == max).
//
// Kernel 1: streaming fused pass, 2 pixels/thread (float2 per class),
//           shared-memory bin accumulation, per-block partials to scratch.
// Kernel 2: deterministic tree reduction of partials -> d_out[0].

#define NCLS   19
#define LOG_HW 19
#define HW     (1 << LOG_HW)          // 512*1024
#define NPIX   (8 * HW)               // 4194304
#define NPAIRS (NPIX / 2)
#define NTHR   256
#define NBLK   (NPAIRS / NTHR)        // 8192
#define NBINS  15

__device__ float g_partial[NBINS * NBLK];

__global__ void ece_main(const float* __restrict__ logits,
                         const int* __restrict__ labels) {
    __shared__ float sS[NBINS];
    const int tid = threadIdx.x;
    if (tid < NBINS) sS[tid] = 0.0f;
    __syncthreads();

    const int t  = blockIdx.x * NTHR + tid;   // pixel-pair index
    const int p0 = t << 1;                    // even pixel
    const int n  = p0 >> LOG_HW;
    const int q  = p0 & (HW - 1);
    const float* base = logits + n * (NCLS * HW) + q;

    // Load 19 classes x 2 pixels (coalesced LDG.64 per class).
    float2 v[NCLS];
#pragma unroll
    for (int c = 0; c < NCLS; ++c)
        v[c] = *(const float2*)(base + c * HW);

    // Labels: two consecutive int32 -> one 8B load.
    const int2 lab = ((const int2*)labels)[t];
    const int l0 = lab.x;
    const int l1 = lab.y;

    // Gather the label-class logit (lines already resident from class loads).
    const float xl0 = base[l0 * HW];
    const float xl1 = base[l1 * HW + 1];

    // Pass 1: max over classes.
    float m0 = v[0].x, m1 = v[0].y;
#pragma unroll
    for (int c = 1; c < NCLS; ++c) {
        m0 = fmaxf(m0, v[c].x);
        m1 = fmaxf(m1, v[c].y);
    }

    // Pass 2: sum exp(x - m).  conf = 1/s.
    float s0 = 0.0f, s1 = 0.0f;
#pragma unroll
    for (int c = 0; c < NCLS; ++c) {
        s0 += __expf(v[c].x - m0);
        s1 += __expf(v[c].y - m1);
    }
    const float conf0 = __fdividef(1.0f, s0);
    const float conf1 = __fdividef(1.0f, s1);

    // correct = (label logit == max)  [argmax-tie divergence: negligible]
    const float val0 = conf0 - ((xl0 == m0) ? 1.0f : 0.0f);
    const float val1 = conf1 - ((xl1 == m1) ? 1.0f : 0.0f);

    // bin = clamp(ceil(conf*15) - 1, 0, 14)  ==  searchsorted(left)-1
    int b0 = (int)ceilf(conf0 * 15.0f) - 1;
    int b1 = (int)ceilf(conf1 * 15.0f) - 1;
    b0 = min(max(b0, 0), NBINS - 1);
    b1 = min(max(b1, 0), NBINS - 1);

    atomicAdd(&sS[b0], val0);
    atomicAdd(&sS[b1], val1);
    __syncthreads();

    if (tid < NBINS)
        g_partial[tid * NBLK + blockIdx.x] = sS[tid];
}

__global__ void ece_reduce(float* __restrict__ out) {
    // 15 warps: warp w reduces bin w over all NBLK partials.
    const int w    = threadIdx.x >> 5;
    const int lane = threadIdx.x & 31;

    const float4* g4 = (const float4*)(g_partial + w * NBLK);
    float4 a = make_float4(0.f, 0.f, 0.f, 0.f);
    for (int j = lane; j < NBLK / 4; j += 32) {
        float4 x = g4[j];
        a.x += x.x; a.y += x.y; a.z += x.z; a.w += x.w;
    }
    float s = (a.x + a.y) + (a.z + a.w);
#pragma unroll
    for (int o = 16; o > 0; o >>= 1)
        s += __shfl_down_sync(0xffffffffu, s, o);

    __shared__ float red[NBINS];
    if (lane == 0) red[w] = s;
    __syncthreads();

    if (threadIdx.x == 0) {
        float e = 0.0f;
#pragma unroll
        for (int i = 0; i < NBINS; ++i) e += fabsf(red[i]);
        out[0] = e * (1.0f / (float)NPIX);
    }
}

extern "C" void kernel_launch(void* const* d_in, const int* in_sizes, int n_in,
                              void* d_out, int out_size) {
    const float* logits = (const float*)d_in[0];
    const int*   labels = (const int*)d_in[1];
    float*       out    = (float*)d_out;

    ece_main<<<NBLK, NTHR>>>(logits, labels);
    ece_reduce<<<1, NBINS * 32>>>(out);
}